// round 1
// baseline (speedup 1.0000x reference)
#include <cuda_runtime.h>
#include <cuda_bf16.h>
#include <math.h>

#define Tdim 4096
#define Hdim 2048
#define Idim 1024
#define Edim 8
#define CAP  9216   // 8192 assignments + 8 experts * 128 padding, multiple of 128

// ---------------- scratch (static device globals; no allocation) ----------------
__device__ float g_h[(size_t)CAP * Idim];     // SwiGLU activations, per slot
__device__ int   g_tok[CAP];                  // slot -> token (-1 = padding)
__device__ float g_gate[CAP];                 // slot -> gate
__device__ int   g_cnt[Edim];
__device__ int   g_off[Edim + 1];             // padded per-expert slot offsets
__device__ int   g_fill[Edim];
__device__ int   g_eidx[Tdim * 2];
__device__ float g_gates[Tdim * 2];

// ---------------- init: zero out, counts, and slot map ----------------
__global__ void init_kernel(float* __restrict__ out) {
    int i = blockIdx.x * blockDim.x + threadIdx.x;
    if (i < Tdim * Hdim) out[i] = 0.f;
    if (i < CAP)  g_tok[i] = -1;
    if (i < Edim) g_cnt[i] = 0;
}

// ---------------- router: logits -> softmax -> top2 ----------------
__global__ void router_kernel(const float* __restrict__ x,
                              const float* __restrict__ rw) {
    const int t   = blockIdx.x;
    const int tid = threadIdx.x;
    float acc[Edim];
#pragma unroll
    for (int e = 0; e < Edim; e++) acc[e] = 0.f;
    const float* xr = x + (size_t)t * Hdim;
    for (int h = tid; h < Hdim; h += 256) {
        float xv = xr[h];
#pragma unroll
        for (int e = 0; e < Edim; e++)
            acc[e] = fmaf(xv, rw[e * Hdim + h], acc[e]);
    }
#pragma unroll
    for (int e = 0; e < Edim; e++)
#pragma unroll
        for (int o = 16; o > 0; o >>= 1)
            acc[e] += __shfl_down_sync(0xffffffffu, acc[e], o);
    __shared__ float s[8][Edim];
    int w = tid >> 5, l = tid & 31;
    if (l == 0)
#pragma unroll
        for (int e = 0; e < Edim; e++) s[w][e] = acc[e];
    __syncthreads();
    if (tid == 0) {
        float logit[Edim];
#pragma unroll
        for (int e = 0; e < Edim; e++) {
            float v = 0.f;
#pragma unroll
            for (int ww = 0; ww < 8; ww++) v += s[ww][e];
            logit[e] = v;
        }
        float m = logit[0];
#pragma unroll
        for (int e = 1; e < Edim; e++) m = fmaxf(m, logit[e]);
        float p[Edim]; float sum = 0.f;
#pragma unroll
        for (int e = 0; e < Edim; e++) { p[e] = expf(logit[e] - m); sum += p[e]; }
        float inv = 1.f / sum;
#pragma unroll
        for (int e = 0; e < Edim; e++) p[e] *= inv;
        // top-2, ties -> lowest index (strict >)
        int i0 = 0; float p0 = p[0];
#pragma unroll
        for (int e = 1; e < Edim; e++) if (p[e] > p0) { p0 = p[e]; i0 = e; }
        int i1 = -1; float p1 = -1.f;
#pragma unroll
        for (int e = 0; e < Edim; e++)
            if (e != i0 && p[e] > p1) { p1 = p[e]; i1 = e; }
        g_eidx[t * 2 + 0] = i0;  g_gates[t * 2 + 0] = p0;
        g_eidx[t * 2 + 1] = i1;  g_gates[t * 2 + 1] = p1;
        atomicAdd(&g_cnt[i0], 1);
        atomicAdd(&g_cnt[i1], 1);
    }
}

// ---------------- offsets: pad each expert to 128 ----------------
__global__ void offsets_kernel() {
    g_off[0] = 0;
#pragma unroll
    for (int e = 0; e < Edim; e++) {
        g_off[e + 1] = g_off[e] + ((g_cnt[e] + 127) & ~127);
        g_fill[e] = 0;
    }
}

// ---------------- scatter tokens into slots ----------------
__global__ void scatter_kernel() {
    int t = blockIdx.x * blockDim.x + threadIdx.x;
    if (t >= Tdim) return;
#pragma unroll
    for (int k = 0; k < 2; k++) {
        int e = g_eidx[t * 2 + k];
        int pos = g_off[e] + atomicAdd(&g_fill[e], 1);
        g_tok[pos]  = t;
        g_gate[pos] = g_gates[t * 2 + k];
    }
}

// ---------------- GEMM1: up = X_gathered @ W1^T, fused SwiGLU -> g_h ----------------
// C[slot, f] = sum_h x[tok(slot), h] * w1[e, f, h]; h_buf[slot, f/2] = up_odd*silu(up_even)
__global__ __launch_bounds__(256, 2)
void gemm1_kernel(const float* __restrict__ x, const float* __restrict__ w1) {
    __shared__ float As[8][128];
    __shared__ float Bs[8][128];
    __shared__ int   toks[128];
    const int bm  = blockIdx.x * 128;      // slot base
    const int bn  = blockIdx.y * 128;      // f base
    const int tid = threadIdx.x;
    int e = 0;
#pragma unroll
    for (int i = 1; i < Edim; i++) if (bm >= g_off[i]) e = i;
    if (tid < 128) toks[tid] = g_tok[bm + tid];
    __syncthreads();

    const int lr = tid >> 1;
    const int lc = (tid & 1) * 4;
    const int ty = tid >> 4, tx = tid & 15;
    const int ta = toks[lr];
    const float* Ap = (ta >= 0) ? (x + (size_t)ta * Hdim) : nullptr;
    const float* Bp = w1 + ((size_t)e * (2 * Idim) + bn + lr) * Hdim;

    float acc[8][8];
#pragma unroll
    for (int i = 0; i < 8; i++)
#pragma unroll
        for (int j = 0; j < 8; j++) acc[i][j] = 0.f;

    for (int k0 = 0; k0 < Hdim; k0 += 8) {
        float4 av = Ap ? *(const float4*)(Ap + k0 + lc) : make_float4(0.f, 0.f, 0.f, 0.f);
        float4 bv = *(const float4*)(Bp + k0 + lc);
        As[lc + 0][lr] = av.x; As[lc + 1][lr] = av.y;
        As[lc + 2][lr] = av.z; As[lc + 3][lr] = av.w;
        Bs[lc + 0][lr] = bv.x; Bs[lc + 1][lr] = bv.y;
        Bs[lc + 2][lr] = bv.z; Bs[lc + 3][lr] = bv.w;
        __syncthreads();
#pragma unroll
        for (int k = 0; k < 8; k++) {
            float4 a0 = *(const float4*)&As[k][ty * 8];
            float4 a1 = *(const float4*)&As[k][ty * 8 + 4];
            float4 b0 = *(const float4*)&Bs[k][tx * 8];
            float4 b1 = *(const float4*)&Bs[k][tx * 8 + 4];
            float ra[8] = {a0.x, a0.y, a0.z, a0.w, a1.x, a1.y, a1.z, a1.w};
            float rb[8] = {b0.x, b0.y, b0.z, b0.w, b1.x, b1.y, b1.z, b1.w};
#pragma unroll
            for (int i = 0; i < 8; i++)
#pragma unroll
                for (int j = 0; j < 8; j++)
                    acc[i][j] = fmaf(ra[i], rb[j], acc[i][j]);
        }
        __syncthreads();
    }

    // SwiGLU epilogue: pairs (even,odd) of f live in this thread's 8 contiguous cols
#pragma unroll
    for (int i = 0; i < 8; i++) {
        int slot = bm + ty * 8 + i;
        float* hr = g_h + (size_t)slot * Idim + ((bn + tx * 8) >> 1);
#pragma unroll
        for (int j = 0; j < 4; j++) {
            float gg = acc[i][2 * j];
            float uu = acc[i][2 * j + 1];
            hr[j] = uu * (gg / (1.f + expf(-gg)));
        }
    }
}

// ---------------- GEMM2: y = h @ W2^T, epilogue atomicAdd gate*y into out ----------------
// C[slot, hh] = sum_i g_h[slot, i] * w2[e, hh, i]
__global__ __launch_bounds__(256, 2)
void gemm2_kernel(const float* __restrict__ w2, float* __restrict__ out) {
    __shared__ float As[8][128];
    __shared__ float Bs[8][128];
    const int bm  = blockIdx.x * 128;      // slot base
    const int bn  = blockIdx.y * 128;      // hh base
    const int tid = threadIdx.x;
    int e = 0;
#pragma unroll
    for (int i = 1; i < Edim; i++) if (bm >= g_off[i]) e = i;

    const int lr = tid >> 1;
    const int lc = (tid & 1) * 4;
    const int ty = tid >> 4, tx = tid & 15;
    const float* Ap = g_h + (size_t)(bm + lr) * Idim;
    const float* Bp = w2 + ((size_t)e * Hdim + bn + lr) * Idim;

    float acc[8][8];
#pragma unroll
    for (int i = 0; i < 8; i++)
#pragma unroll
        for (int j = 0; j < 8; j++) acc[i][j] = 0.f;

    for (int k0 = 0; k0 < Idim; k0 += 8) {
        float4 av = *(const float4*)(Ap + k0 + lc);
        float4 bv = *(const float4*)(Bp + k0 + lc);
        As[lc + 0][lr] = av.x; As[lc + 1][lr] = av.y;
        As[lc + 2][lr] = av.z; As[lc + 3][lr] = av.w;
        Bs[lc + 0][lr] = bv.x; Bs[lc + 1][lr] = bv.y;
        Bs[lc + 2][lr] = bv.z; Bs[lc + 3][lr] = bv.w;
        __syncthreads();
#pragma unroll
        for (int k = 0; k < 8; k++) {
            float4 a0 = *(const float4*)&As[k][ty * 8];
            float4 a1 = *(const float4*)&As[k][ty * 8 + 4];
            float4 b0 = *(const float4*)&Bs[k][tx * 8];
            float4 b1 = *(const float4*)&Bs[k][tx * 8 + 4];
            float ra[8] = {a0.x, a0.y, a0.z, a0.w, a1.x, a1.y, a1.z, a1.w};
            float rb[8] = {b0.x, b0.y, b0.z, b0.w, b1.x, b1.y, b1.z, b1.w};
#pragma unroll
            for (int i = 0; i < 8; i++)
#pragma unroll
                for (int j = 0; j < 8; j++)
                    acc[i][j] = fmaf(ra[i], rb[j], acc[i][j]);
        }
        __syncthreads();
    }

#pragma unroll
    for (int i = 0; i < 8; i++) {
        int slot = bm + ty * 8 + i;
        int t = g_tok[slot];
        if (t < 0) continue;
        float gt = g_gate[slot];
        float* orow = out + (size_t)t * Hdim + bn + tx * 8;
#pragma unroll
        for (int j = 0; j < 8; j++)
            atomicAdd(&orow[j], gt * acc[i][j]);
    }
}

// ---------------- launch ----------------
extern "C" void kernel_launch(void* const* d_in, const int* in_sizes, int n_in,
                              void* d_out, int out_size) {
    const float* x  = (const float*)d_in[0];
    const float* rw = (const float*)d_in[1];
    const float* w1 = (const float*)d_in[2];
    const float* w2 = (const float*)d_in[3];
    float* out = (float*)d_out;

    init_kernel<<<(Tdim * Hdim + 255) / 256, 256>>>(out);
    router_kernel<<<Tdim, 256>>>(x, rw);
    offsets_kernel<<<1, 1>>>();
    scatter_kernel<<<(Tdim + 255) / 256, 256>>>();
    dim3 g1(CAP / 128, (2 * Idim) / 128);
    gemm1_kernel<<<g1, 256>>>(x, w1);
    dim3 g2(CAP / 128, Hdim / 128);
    gemm2_kernel<<<g2, 256>>>(w2, out);
}

// round 3
// speedup vs baseline: 2.8147x; 2.8147x over previous
#include <cuda_runtime.h>
#include <cuda_bf16.h>
#include <math.h>
#include <stdint.h>

#define Tdim 4096
#define Hdim 2048
#define Idim 1024
#define Edim 8
#define CAP  9216   // 8192 assignments + 8*128 padding

// ---------------- device scratch ----------------
__device__ __nv_bfloat16 g_w1h[(size_t)Edim * 2 * Idim * Hdim];
__device__ __nv_bfloat16 g_w1l[(size_t)Edim * 2 * Idim * Hdim];
__device__ __nv_bfloat16 g_w2h[(size_t)Edim * Hdim * Idim];
__device__ __nv_bfloat16 g_w2l[(size_t)Edim * Hdim * Idim];
__device__ __nv_bfloat16 g_xh[(size_t)Tdim * Hdim];
__device__ __nv_bfloat16 g_xl[(size_t)Tdim * Hdim];
__device__ __nv_bfloat16 g_hh[(size_t)CAP * Idim];
__device__ __nv_bfloat16 g_hl[(size_t)CAP * Idim];
__device__ float g_y[(size_t)CAP * Hdim];
__device__ int   g_tok[CAP];
__device__ float g_gate[CAP];
__device__ int   g_cnt[Edim];
__device__ int   g_off[Edim + 1];
__device__ int   g_fill[Edim];
__device__ int   g_eidx[Tdim * 2];
__device__ float g_gates[Tdim * 2];
__device__ int   g_slot[Tdim * 2];

// ---------------- PTX helpers (plain sm_80-era PTX only) ----------------
__device__ __forceinline__ uint32_t su32(const void* p) {
    uint32_t a;
    asm("{ .reg .u64 t; cvta.to.shared.u64 t, %1; cvt.u32.u64 %0, t; }" : "=r"(a) : "l"(p));
    return a;
}
__device__ __forceinline__ void cpa16(uint32_t dst, const void* src, uint32_t sz) {
    asm volatile("cp.async.cg.shared.global [%0], [%1], 16, %2;\n"
                 :: "r"(dst), "l"(src), "r"(sz) : "memory");
}
__device__ __forceinline__ void ldsm4(uint32_t a, uint32_t& r0, uint32_t& r1,
                                      uint32_t& r2, uint32_t& r3) {
    asm volatile("ldmatrix.sync.aligned.m8n8.x4.shared.b16 {%0,%1,%2,%3}, [%4];"
                 : "=r"(r0), "=r"(r1), "=r"(r2), "=r"(r3) : "r"(a));
}
__device__ __forceinline__ void mma16816(float* d, const uint32_t* a, const uint32_t* b) {
    asm volatile("mma.sync.aligned.m16n8k16.row.col.f32.bf16.bf16.f32 "
                 "{%0,%1,%2,%3}, {%4,%5,%6,%7}, {%8,%9}, {%0,%1,%2,%3};"
                 : "+f"(d[0]), "+f"(d[1]), "+f"(d[2]), "+f"(d[3])
                 : "r"(a[0]), "r"(a[1]), "r"(a[2]), "r"(a[3]), "r"(b[0]), "r"(b[1]));
}

// SMEM stage layout: 4 matrices (Ah, Al, Bh, Bl), each 128 rows x 80B stride
#define ROWB 80
#define MATB (128 * ROWB)        // 10240
#define AH_OF 0
#define AL_OF (1 * MATB)
#define BH_OF (2 * MATB)
#define BL_OF (3 * MATB)
#define STAGEB (4 * MATB)        // 40960
#define SMEM_SZ (2 * STAGEB)     // 81920

// ---------------- init ----------------
__global__ void init_kernel() {
    int i = blockIdx.x * blockDim.x + threadIdx.x;
    if (i < CAP)  { g_tok[i] = -1; g_gate[i] = 0.f; }
    if (i < Edim) g_cnt[i] = 0;
}

// ---------------- fp32 -> bf16 hi/lo split ----------------
__global__ void conv_split_kernel(const float* __restrict__ s,
                                  __nv_bfloat16* __restrict__ hi,
                                  __nv_bfloat16* __restrict__ lo, size_t n) {
    size_t i = ((size_t)blockIdx.x * 256 + threadIdx.x) * 4;
    if (i >= n) return;
    float4 v = *(const float4*)(s + i);
    __nv_bfloat16 h0 = __float2bfloat16(v.x), h1 = __float2bfloat16(v.y);
    __nv_bfloat16 h2 = __float2bfloat16(v.z), h3 = __float2bfloat16(v.w);
    __nv_bfloat16 l0 = __float2bfloat16(v.x - __bfloat162float(h0));
    __nv_bfloat16 l1 = __float2bfloat16(v.y - __bfloat162float(h1));
    __nv_bfloat16 l2 = __float2bfloat16(v.z - __bfloat162float(h2));
    __nv_bfloat16 l3 = __float2bfloat16(v.w - __bfloat162float(h3));
    *(__nv_bfloat162*)(hi + i)     = __nv_bfloat162(h0, h1);
    *(__nv_bfloat162*)(hi + i + 2) = __nv_bfloat162(h2, h3);
    *(__nv_bfloat162*)(lo + i)     = __nv_bfloat162(l0, l1);
    *(__nv_bfloat162*)(lo + i + 2) = __nv_bfloat162(l2, l3);
}

// ---------------- router ----------------
__global__ void router_kernel(const float* __restrict__ x,
                              const float* __restrict__ rw) {
    const int t   = blockIdx.x;
    const int tid = threadIdx.x;
    float acc[Edim];
#pragma unroll
    for (int e = 0; e < Edim; e++) acc[e] = 0.f;
    const float* xr = x + (size_t)t * Hdim;
    for (int h = tid; h < Hdim; h += 256) {
        float xv = xr[h];
#pragma unroll
        for (int e = 0; e < Edim; e++)
            acc[e] = fmaf(xv, rw[e * Hdim + h], acc[e]);
    }
#pragma unroll
    for (int e = 0; e < Edim; e++)
#pragma unroll
        for (int o = 16; o > 0; o >>= 1)
            acc[e] += __shfl_down_sync(0xffffffffu, acc[e], o);
    __shared__ float s[8][Edim];
    int w = tid >> 5, l = tid & 31;
    if (l == 0)
#pragma unroll
        for (int e = 0; e < Edim; e++) s[w][e] = acc[e];
    __syncthreads();
    if (tid == 0) {
        float logit[Edim];
#pragma unroll
        for (int e = 0; e < Edim; e++) {
            float v = 0.f;
#pragma unroll
            for (int ww = 0; ww < 8; ww++) v += s[ww][e];
            logit[e] = v;
        }
        float m = logit[0];
#pragma unroll
        for (int e = 1; e < Edim; e++) m = fmaxf(m, logit[e]);
        float p[Edim]; float sum = 0.f;
#pragma unroll
        for (int e = 0; e < Edim; e++) { p[e] = expf(logit[e] - m); sum += p[e]; }
        float inv = 1.f / sum;
#pragma unroll
        for (int e = 0; e < Edim; e++) p[e] *= inv;
        int i0 = 0; float p0 = p[0];
#pragma unroll
        for (int e = 1; e < Edim; e++) if (p[e] > p0) { p0 = p[e]; i0 = e; }
        int i1 = -1; float p1 = -1.f;
#pragma unroll
        for (int e = 0; e < Edim; e++)
            if (e != i0 && p[e] > p1) { p1 = p[e]; i1 = e; }
        g_eidx[t * 2 + 0] = i0;  g_gates[t * 2 + 0] = p0;
        g_eidx[t * 2 + 1] = i1;  g_gates[t * 2 + 1] = p1;
        atomicAdd(&g_cnt[i0], 1);
        atomicAdd(&g_cnt[i1], 1);
    }
}

__global__ void offsets_kernel() {
    g_off[0] = 0;
#pragma unroll
    for (int e = 0; e < Edim; e++) {
        g_off[e + 1] = g_off[e] + ((g_cnt[e] + 127) & ~127);
        g_fill[e] = 0;
    }
}

__global__ void scatter_kernel() {
    int t = blockIdx.x * blockDim.x + threadIdx.x;
    if (t >= Tdim) return;
#pragma unroll
    for (int k = 0; k < 2; k++) {
        int e = g_eidx[t * 2 + k];
        int pos = g_off[e] + atomicAdd(&g_fill[e], 1);
        g_tok[pos]  = t;
        g_gate[pos] = g_gates[t * 2 + k];
        g_slot[t * 2 + k] = pos;
    }
}

// ================= GEMM1: up = gather(x) @ w1^T (3x bf16 mma), SwiGLU*gate =================
__global__ void __launch_bounds__(256, 2) gemm1_kernel() {
    extern __shared__ __align__(128) char smem[];
    __shared__ int   toks[128];
    __shared__ float sgate[128];
    const uint32_t sb = su32(smem);
    const int tid = threadIdx.x, lane = tid & 31, wid = tid >> 5;
    const int wm = (wid & 1) * 64, wn = (wid >> 1) * 32;
    const int bm = blockIdx.x * 128, bn = blockIdx.y * 128;
    if (bm >= g_off[Edim]) return;
    int e = 0;
#pragma unroll
    for (int i = 1; i < Edim; i++) if (bm >= g_off[i]) e = i;
    if (tid < 128) { toks[tid] = g_tok[bm + tid]; sgate[tid] = g_gate[bm + tid]; }
    __syncthreads();

    const __nv_bfloat16* w1h_b = g_w1h + ((size_t)(e * 2 * Idim) + bn) * Hdim;
    const __nv_bfloat16* w1l_b = g_w1l + ((size_t)(e * 2 * Idim) + bn) * Hdim;

    auto load_stage = [&](int kc, int s) {
        const uint32_t base = sb + s * STAGEB;
        const int k0 = kc * 32;
#pragma unroll
        for (int i = 0; i < 2; i++) {
            int idx = tid + i * 256;
            int r = idx >> 2, c = idx & 3;
            int t = toks[r];
            uint32_t sz = (t >= 0) ? 16u : 0u;
            size_t tt = (t >= 0) ? (size_t)t : 0;
            uint32_t dof = r * ROWB + c * 16;
            cpa16(base + AH_OF + dof, g_xh + tt * Hdim + k0 + c * 8, sz);
            cpa16(base + AL_OF + dof, g_xl + tt * Hdim + k0 + c * 8, sz);
            cpa16(base + BH_OF + dof, w1h_b + (size_t)r * Hdim + k0 + c * 8, 16u);
            cpa16(base + BL_OF + dof, w1l_b + (size_t)r * Hdim + k0 + c * 8, 16u);
        }
        asm volatile("cp.async.commit_group;" ::: "memory");
    };

    float acc[4][4][4];
#pragma unroll
    for (int a = 0; a < 4; a++)
#pragma unroll
        for (int b = 0; b < 4; b++)
#pragma unroll
            for (int c = 0; c < 4; c++) acc[a][b][c] = 0.f;

    const uint32_t a_off = (lane & 15) * ROWB + (lane >> 4) * 16;
    const uint32_t b_off = (((lane >> 4) << 3) | (lane & 7)) * ROWB + ((lane >> 3) & 1) * 16;

    const int NT = Hdim / 32;
    load_stage(0, 0);
    for (int kc = 0; kc < NT; kc++) {
        int s = kc & 1;
        if (kc + 1 < NT) {
            load_stage(kc + 1, s ^ 1);
            asm volatile("cp.async.wait_group 1;" ::: "memory");
        } else {
            asm volatile("cp.async.wait_group 0;" ::: "memory");
        }
        __syncthreads();
        const uint32_t stg = sb + s * STAGEB;
#pragma unroll
        for (int p = 0; p < 2; p++) {
            uint32_t Bh[8], Bl[8];
#pragma unroll
            for (int n2 = 0; n2 < 2; n2++) {
                uint32_t ba = stg + (wn + n2 * 16) * ROWB + p * 32 + b_off;
                ldsm4(ba + BH_OF, Bh[n2 * 4 + 0], Bh[n2 * 4 + 1], Bh[n2 * 4 + 2], Bh[n2 * 4 + 3]);
                ldsm4(ba + BL_OF, Bl[n2 * 4 + 0], Bl[n2 * 4 + 1], Bl[n2 * 4 + 2], Bl[n2 * 4 + 3]);
            }
#pragma unroll
            for (int mt = 0; mt < 4; mt++) {
                uint32_t ah[4], al[4];
                uint32_t aa = stg + (wm + mt * 16) * ROWB + p * 32 + a_off;
                ldsm4(aa + AH_OF, ah[0], ah[1], ah[2], ah[3]);
                ldsm4(aa + AL_OF, al[0], al[1], al[2], al[3]);
#pragma unroll
                for (int nt = 0; nt < 4; nt++) {
                    mma16816(acc[mt][nt], ah, &Bh[nt * 2]);
                    mma16816(acc[mt][nt], ah, &Bl[nt * 2]);
                    mma16816(acc[mt][nt], al, &Bh[nt * 2]);
                }
            }
        }
        __syncthreads();
    }

    // epilogue: gate * u * silu(g) -> bf16 hi/lo
    const int g = lane >> 2, tg = lane & 3;
#pragma unroll
    for (int mt = 0; mt < 4; mt++) {
        int r0 = wm + mt * 16 + g;
        int slot0 = bm + r0;
        float gate0 = sgate[r0], gate1 = sgate[r0 + 8];
#pragma unroll
        for (int nt = 0; nt < 4; nt++) {
            int hcol = (bn >> 1) + (wn >> 1) + nt * 4 + tg;
            float gv0 = acc[mt][nt][0], uv0 = acc[mt][nt][1];
            float gv1 = acc[mt][nt][2], uv1 = acc[mt][nt][3];
            float h0 = gate0 * uv0 * (gv0 / (1.f + __expf(-gv0)));
            float h1 = gate1 * uv1 * (gv1 / (1.f + __expf(-gv1)));
            __nv_bfloat16 hh0 = __float2bfloat16(h0);
            __nv_bfloat16 hh1 = __float2bfloat16(h1);
            g_hh[(size_t)slot0 * Idim + hcol]       = hh0;
            g_hl[(size_t)slot0 * Idim + hcol]       = __float2bfloat16(h0 - __bfloat162float(hh0));
            g_hh[(size_t)(slot0 + 8) * Idim + hcol] = hh1;
            g_hl[(size_t)(slot0 + 8) * Idim + hcol] = __float2bfloat16(h1 - __bfloat162float(hh1));
        }
    }
}

// ================= GEMM2: y = h @ w2^T (3x bf16 mma) -> g_y =================
__global__ void __launch_bounds__(256, 2) gemm2_kernel() {
    extern __shared__ __align__(128) char smem[];
    const uint32_t sb = su32(smem);
    const int tid = threadIdx.x, lane = tid & 31, wid = tid >> 5;
    const int wm = (wid & 1) * 64, wn = (wid >> 1) * 32;
    const int bm = blockIdx.x * 128, bn = blockIdx.y * 128;
    if (bm >= g_off[Edim]) return;
    int e = 0;
#pragma unroll
    for (int i = 1; i < Edim; i++) if (bm >= g_off[i]) e = i;

    const __nv_bfloat16* w2h_b = g_w2h + ((size_t)(e * Hdim) + bn) * Idim;
    const __nv_bfloat16* w2l_b = g_w2l + ((size_t)(e * Hdim) + bn) * Idim;

    auto load_stage = [&](int kc, int s) {
        const uint32_t base = sb + s * STAGEB;
        const int k0 = kc * 32;
#pragma unroll
        for (int i = 0; i < 2; i++) {
            int idx = tid + i * 256;
            int r = idx >> 2, c = idx & 3;
            uint32_t dof = r * ROWB + c * 16;
            cpa16(base + AH_OF + dof, g_hh + (size_t)(bm + r) * Idim + k0 + c * 8, 16u);
            cpa16(base + AL_OF + dof, g_hl + (size_t)(bm + r) * Idim + k0 + c * 8, 16u);
            cpa16(base + BH_OF + dof, w2h_b + (size_t)r * Idim + k0 + c * 8, 16u);
            cpa16(base + BL_OF + dof, w2l_b + (size_t)r * Idim + k0 + c * 8, 16u);
        }
        asm volatile("cp.async.commit_group;" ::: "memory");
    };

    float acc[4][4][4];
#pragma unroll
    for (int a = 0; a < 4; a++)
#pragma unroll
        for (int b = 0; b < 4; b++)
#pragma unroll
            for (int c = 0; c < 4; c++) acc[a][b][c] = 0.f;

    const uint32_t a_off = (lane & 15) * ROWB + (lane >> 4) * 16;
    const uint32_t b_off = (((lane >> 4) << 3) | (lane & 7)) * ROWB + ((lane >> 3) & 1) * 16;

    const int NT = Idim / 32;
    load_stage(0, 0);
    for (int kc = 0; kc < NT; kc++) {
        int s = kc & 1;
        if (kc + 1 < NT) {
            load_stage(kc + 1, s ^ 1);
            asm volatile("cp.async.wait_group 1;" ::: "memory");
        } else {
            asm volatile("cp.async.wait_group 0;" ::: "memory");
        }
        __syncthreads();
        const uint32_t stg = sb + s * STAGEB;
#pragma unroll
        for (int p = 0; p < 2; p++) {
            uint32_t Bh[8], Bl[8];
#pragma unroll
            for (int n2 = 0; n2 < 2; n2++) {
                uint32_t ba = stg + (wn + n2 * 16) * ROWB + p * 32 + b_off;
                ldsm4(ba + BH_OF, Bh[n2 * 4 + 0], Bh[n2 * 4 + 1], Bh[n2 * 4 + 2], Bh[n2 * 4 + 3]);
                ldsm4(ba + BL_OF, Bl[n2 * 4 + 0], Bl[n2 * 4 + 1], Bl[n2 * 4 + 2], Bl[n2 * 4 + 3]);
            }
#pragma unroll
            for (int mt = 0; mt < 4; mt++) {
                uint32_t ah[4], al[4];
                uint32_t aa = stg + (wm + mt * 16) * ROWB + p * 32 + a_off;
                ldsm4(aa + AH_OF, ah[0], ah[1], ah[2], ah[3]);
                ldsm4(aa + AL_OF, al[0], al[1], al[2], al[3]);
#pragma unroll
                for (int nt = 0; nt < 4; nt++) {
                    mma16816(acc[mt][nt], ah, &Bh[nt * 2]);
                    mma16816(acc[mt][nt], ah, &Bl[nt * 2]);
                    mma16816(acc[mt][nt], al, &Bh[nt * 2]);
                }
            }
        }
        __syncthreads();
    }

    // epilogue: write y rows (fp32, float2 per thread)
    const int g = lane >> 2, tg = lane & 3;
#pragma unroll
    for (int mt = 0; mt < 4; mt++) {
        int slot0 = bm + wm + mt * 16 + g;
#pragma unroll
        for (int nt = 0; nt < 4; nt++) {
            int col = bn + wn + nt * 8 + 2 * tg;
            *(float2*)(g_y + (size_t)slot0 * Hdim + col) =
                make_float2(acc[mt][nt][0], acc[mt][nt][1]);
            *(float2*)(g_y + (size_t)(slot0 + 8) * Hdim + col) =
                make_float2(acc[mt][nt][2], acc[mt][nt][3]);
        }
    }
}

// ---------------- combine: out[t] = y[slot0] + y[slot1] ----------------
__global__ void combine_kernel(float* __restrict__ out) {
    int i = blockIdx.x * 256 + threadIdx.x;   // per float4
    int t  = i / (Hdim / 4);
    int c4 = i % (Hdim / 4);
    int s0 = g_slot[t * 2], s1 = g_slot[t * 2 + 1];
    float4 a = *(const float4*)(g_y + (size_t)s0 * Hdim + c4 * 4);
    float4 b = *(const float4*)(g_y + (size_t)s1 * Hdim + c4 * 4);
    *(float4*)(out + (size_t)t * Hdim + c4 * 4) =
        make_float4(a.x + b.x, a.y + b.y, a.z + b.z, a.w + b.w);
}

// ---------------- launch ----------------
extern "C" void kernel_launch(void* const* d_in, const int* in_sizes, int n_in,
                              void* d_out, int out_size) {
    const float* x  = (const float*)d_in[0];
    const float* rw = (const float*)d_in[1];
    const float* w1 = (const float*)d_in[2];
    const float* w2 = (const float*)d_in[3];
    float* out = (float*)d_out;

    cudaFuncSetAttribute(gemm1_kernel, cudaFuncAttributeMaxDynamicSharedMemorySize, SMEM_SZ);
    cudaFuncSetAttribute(gemm2_kernel, cudaFuncAttributeMaxDynamicSharedMemorySize, SMEM_SZ);

    __nv_bfloat16 *xh, *xl, *w1h, *w1l, *w2h, *w2l;
    cudaGetSymbolAddress((void**)&xh,  g_xh);
    cudaGetSymbolAddress((void**)&xl,  g_xl);
    cudaGetSymbolAddress((void**)&w1h, g_w1h);
    cudaGetSymbolAddress((void**)&w1l, g_w1l);
    cudaGetSymbolAddress((void**)&w2h, g_w2h);
    cudaGetSymbolAddress((void**)&w2l, g_w2l);

    init_kernel<<<(CAP + 255) / 256, 256>>>();
    {
        size_t n = (size_t)Tdim * Hdim;
        conv_split_kernel<<<(unsigned)((n / 4 + 255) / 256), 256>>>(x, xh, xl, n);
    }
    {
        size_t n = (size_t)Edim * 2 * Idim * Hdim;
        conv_split_kernel<<<(unsigned)((n / 4 + 255) / 256), 256>>>(w1, w1h, w1l, n);
    }
    {
        size_t n = (size_t)Edim * Hdim * Idim;
        conv_split_kernel<<<(unsigned)((n / 4 + 255) / 256), 256>>>(w2, w2h, w2l, n);
    }
    router_kernel<<<Tdim, 256>>>(x, rw);
    offsets_kernel<<<1, 1>>>();
    scatter_kernel<<<(Tdim + 255) / 256, 256>>>();

    dim3 g1(CAP / 128, (2 * Idim) / 128);
    gemm1_kernel<<<g1, 256, SMEM_SZ>>>();
    dim3 g2(CAP / 128, Hdim / 128);
    gemm2_kernel<<<g2, 256, SMEM_SZ>>>();
    combine_kernel<<<(Tdim * Hdim / 4) / 256, 256>>>(out);
}

// round 5
// speedup vs baseline: 3.8689x; 1.3746x over previous
#include <cuda_runtime.h>
#include <cuda_fp16.h>
#include <math.h>
#include <stdint.h>

#define Tdim 4096
#define Hdim 2048
#define Idim 1024
#define Edim 8
#define CAP  9216   // 8192 assignments + 8*128 padding

// ---------------- device scratch ----------------
__device__ __half g_w1f[(size_t)Edim * 2 * Idim * Hdim];
__device__ __half g_w2f[(size_t)Edim * Hdim * Idim];
__device__ __half g_xh[(size_t)Tdim * Hdim];
__device__ __half g_xl[(size_t)Tdim * Hdim];
__device__ __half g_hh[(size_t)CAP * Idim];
__device__ __half g_hl[(size_t)CAP * Idim];
__device__ float g_y[(size_t)CAP * Hdim];
__device__ int   g_tok[CAP];
__device__ float g_gate[CAP];
__device__ int   g_cnt[Edim];
__device__ int   g_off[Edim + 1];
__device__ int   g_fill[Edim];
__device__ int   g_eidx[Tdim * 2];
__device__ float g_gates[Tdim * 2];
__device__ int   g_slot[Tdim * 2];

// ---------------- PTX helpers (plain sm_80-era PTX only) ----------------
__device__ __forceinline__ uint32_t su32(const void* p) {
    uint32_t a;
    asm("{ .reg .u64 t; cvta.to.shared.u64 t, %1; cvt.u32.u64 %0, t; }" : "=r"(a) : "l"(p));
    return a;
}
__device__ __forceinline__ void cpa16(uint32_t dst, const void* src, uint32_t sz) {
    asm volatile("cp.async.cg.shared.global [%0], [%1], 16, %2;\n"
                 :: "r"(dst), "l"(src), "r"(sz) : "memory");
}
__device__ __forceinline__ void ldsm4(uint32_t a, uint32_t& r0, uint32_t& r1,
                                      uint32_t& r2, uint32_t& r3) {
    asm volatile("ldmatrix.sync.aligned.m8n8.x4.shared.b16 {%0,%1,%2,%3}, [%4];"
                 : "=r"(r0), "=r"(r1), "=r"(r2), "=r"(r3) : "r"(a));
}
__device__ __forceinline__ void mma16816(float* d, const uint32_t* a, const uint32_t* b) {
    asm volatile("mma.sync.aligned.m16n8k16.row.col.f32.f16.f16.f32 "
                 "{%0,%1,%2,%3}, {%4,%5,%6,%7}, {%8,%9}, {%0,%1,%2,%3};"
                 : "+f"(d[0]), "+f"(d[1]), "+f"(d[2]), "+f"(d[3])
                 : "r"(a[0]), "r"(a[1]), "r"(a[2]), "r"(a[3]), "r"(b[0]), "r"(b[1]));
}

// SMEM stage layout: 3 matrices (Ah, Al, B), each 128 rows x 80B stride
#define ROWB 80
#define MATB (128 * ROWB)        // 10240
#define AH_OF 0
#define AL_OF (1 * MATB)
#define B_OF  (2 * MATB)
#define STAGEB (3 * MATB)        // 30720
#define SMEM_SZ (2 * STAGEB)     // 61440

// ---------------- init ----------------
__global__ void init_kernel() {
    int i = blockIdx.x * blockDim.x + threadIdx.x;
    if (i < CAP)  { g_tok[i] = -1; g_gate[i] = 0.f; }
    if (i < Edim) g_cnt[i] = 0;
}

// ---------------- fp32 -> fp16 hi/lo split (activations) ----------------
__global__ void conv_split_kernel(const float* __restrict__ s,
                                  __half* __restrict__ hi,
                                  __half* __restrict__ lo, size_t n) {
    size_t i = ((size_t)blockIdx.x * 256 + threadIdx.x) * 4;
    if (i >= n) return;
    float4 v = *(const float4*)(s + i);
    __half h0 = __float2half(v.x), h1 = __float2half(v.y);
    __half h2 = __float2half(v.z), h3 = __float2half(v.w);
    __half l0 = __float2half(v.x - __half2float(h0));
    __half l1 = __float2half(v.y - __half2float(h1));
    __half l2 = __float2half(v.z - __half2float(h2));
    __half l3 = __float2half(v.w - __half2float(h3));
    *(__half2*)(hi + i)     = __halves2half2(h0, h1);
    *(__half2*)(hi + i + 2) = __halves2half2(h2, h3);
    *(__half2*)(lo + i)     = __halves2half2(l0, l1);
    *(__half2*)(lo + i + 2) = __halves2half2(l2, l3);
}

// ---------------- fp32 -> fp16 (weights, single plane) ----------------
__global__ void conv_half_kernel(const float* __restrict__ s,
                                 __half* __restrict__ d, size_t n) {
    size_t i = ((size_t)blockIdx.x * 256 + threadIdx.x) * 4;
    if (i >= n) return;
    float4 v = *(const float4*)(s + i);
    *(__half2*)(d + i)     = __halves2half2(__float2half(v.x), __float2half(v.y));
    *(__half2*)(d + i + 2) = __halves2half2(__float2half(v.z), __float2half(v.w));
}

// ---------------- router ----------------
__global__ void router_kernel(const float* __restrict__ x,
                              const float* __restrict__ rw) {
    const int t   = blockIdx.x;
    const int tid = threadIdx.x;
    float acc[Edim];
#pragma unroll
    for (int e = 0; e < Edim; e++) acc[e] = 0.f;
    const float* xr = x + (size_t)t * Hdim;
    for (int h = tid; h < Hdim; h += 256) {
        float xv = xr[h];
#pragma unroll
        for (int e = 0; e < Edim; e++)
            acc[e] = fmaf(xv, rw[e * Hdim + h], acc[e]);
    }
#pragma unroll
    for (int e = 0; e < Edim; e++)
#pragma unroll
        for (int o = 16; o > 0; o >>= 1)
            acc[e] += __shfl_down_sync(0xffffffffu, acc[e], o);
    __shared__ float s[8][Edim];
    int w = tid >> 5, l = tid & 31;
    if (l == 0)
#pragma unroll
        for (int e = 0; e < Edim; e++) s[w][e] = acc[e];
    __syncthreads();
    if (tid == 0) {
        float logit[Edim];
#pragma unroll
        for (int e = 0; e < Edim; e++) {
            float v = 0.f;
#pragma unroll
            for (int ww = 0; ww < 8; ww++) v += s[ww][e];
            logit[e] = v;
        }
        float m = logit[0];
#pragma unroll
        for (int e = 1; e < Edim; e++) m = fmaxf(m, logit[e]);
        float p[Edim]; float sum = 0.f;
#pragma unroll
        for (int e = 0; e < Edim; e++) { p[e] = expf(logit[e] - m); sum += p[e]; }
        float inv = 1.f / sum;
#pragma unroll
        for (int e = 0; e < Edim; e++) p[e] *= inv;
        int i0 = 0; float p0 = p[0];
#pragma unroll
        for (int e = 1; e < Edim; e++) if (p[e] > p0) { p0 = p[e]; i0 = e; }
        int i1 = -1; float p1 = -1.f;
#pragma unroll
        for (int e = 0; e < Edim; e++)
            if (e != i0 && p[e] > p1) { p1 = p[e]; i1 = e; }
        g_eidx[t * 2 + 0] = i0;  g_gates[t * 2 + 0] = p0;
        g_eidx[t * 2 + 1] = i1;  g_gates[t * 2 + 1] = p1;
        atomicAdd(&g_cnt[i0], 1);
        atomicAdd(&g_cnt[i1], 1);
    }
}

__global__ void offsets_kernel() {
    g_off[0] = 0;
#pragma unroll
    for (int e = 0; e < Edim; e++) {
        g_off[e + 1] = g_off[e] + ((g_cnt[e] + 127) & ~127);
        g_fill[e] = 0;
    }
}

__global__ void scatter_kernel() {
    int t = blockIdx.x * blockDim.x + threadIdx.x;
    if (t >= Tdim) return;
#pragma unroll
    for (int k = 0; k < 2; k++) {
        int e = g_eidx[t * 2 + k];
        int pos = g_off[e] + atomicAdd(&g_fill[e], 1);
        g_tok[pos]  = t;
        g_gate[pos] = g_gates[t * 2 + k];
        g_slot[t * 2 + k] = pos;
    }
}

// ================= GEMM1: up = gather(x) @ w1^T (2x fp16 mma), SwiGLU*gate =================
__global__ void __launch_bounds__(256, 2) gemm1_kernel() {
    extern __shared__ __align__(128) char smem[];
    __shared__ int   toks[128];
    __shared__ float sgate[128];
    const uint32_t sb = su32(smem);
    const int tid = threadIdx.x, lane = tid & 31, wid = tid >> 5;
    const int wm = (wid & 1) * 64, wn = (wid >> 1) * 32;
    const int bm = blockIdx.x * 128, bn = blockIdx.y * 128;
    if (bm >= g_off[Edim]) return;
    int e = 0;
#pragma unroll
    for (int i = 1; i < Edim; i++) if (bm >= g_off[i]) e = i;
    if (tid < 128) { toks[tid] = g_tok[bm + tid]; sgate[tid] = g_gate[bm + tid]; }
    __syncthreads();

    const __half* w1_b = g_w1f + ((size_t)(e * 2 * Idim) + bn) * Hdim;

    auto load_stage = [&](int kc, int s) {
        const uint32_t base = sb + s * STAGEB;
        const int k0 = kc * 32;
#pragma unroll
        for (int i = 0; i < 2; i++) {
            int idx = tid + i * 256;
            int r = idx >> 2, c = idx & 3;
            int t = toks[r];
            uint32_t sz = (t >= 0) ? 16u : 0u;
            size_t tt = (t >= 0) ? (size_t)t : 0;
            uint32_t dof = r * ROWB + c * 16;
            cpa16(base + AH_OF + dof, g_xh + tt * Hdim + k0 + c * 8, sz);
            cpa16(base + AL_OF + dof, g_xl + tt * Hdim + k0 + c * 8, sz);
            cpa16(base + B_OF  + dof, w1_b + (size_t)r * Hdim + k0 + c * 8, 16u);
        }
        asm volatile("cp.async.commit_group;" ::: "memory");
    };

    float acc[4][4][4];
#pragma unroll
    for (int a = 0; a < 4; a++)
#pragma unroll
        for (int b = 0; b < 4; b++)
#pragma unroll
            for (int c = 0; c < 4; c++) acc[a][b][c] = 0.f;

    const uint32_t a_off = (lane & 15) * ROWB + (lane >> 4) * 16;
    const uint32_t b_off = (((lane >> 4) << 3) | (lane & 7)) * ROWB + ((lane >> 3) & 1) * 16;

    const int NT = Hdim / 32;
    load_stage(0, 0);
    for (int kc = 0; kc < NT; kc++) {
        int s = kc & 1;
        if (kc + 1 < NT) {
            load_stage(kc + 1, s ^ 1);
            asm volatile("cp.async.wait_group 1;" ::: "memory");
        } else {
            asm volatile("cp.async.wait_group 0;" ::: "memory");
        }
        __syncthreads();
        const uint32_t stg = sb + s * STAGEB;
#pragma unroll
        for (int p = 0; p < 2; p++) {
            uint32_t Bv[8];
#pragma unroll
            for (int n2 = 0; n2 < 2; n2++) {
                uint32_t ba = stg + B_OF + (wn + n2 * 16) * ROWB + p * 32 + b_off;
                ldsm4(ba, Bv[n2 * 4 + 0], Bv[n2 * 4 + 1], Bv[n2 * 4 + 2], Bv[n2 * 4 + 3]);
            }
#pragma unroll
            for (int mt = 0; mt < 4; mt++) {
                uint32_t ah[4], al[4];
                uint32_t aa = stg + (wm + mt * 16) * ROWB + p * 32 + a_off;
                ldsm4(aa + AH_OF, ah[0], ah[1], ah[2], ah[3]);
                ldsm4(aa + AL_OF, al[0], al[1], al[2], al[3]);
#pragma unroll
                for (int nt = 0; nt < 4; nt++) {
                    mma16816(acc[mt][nt], ah, &Bv[nt * 2]);
                    mma16816(acc[mt][nt], al, &Bv[nt * 2]);
                }
            }
        }
        __syncthreads();
    }

    // epilogue: gate * u * silu(g) -> fp16 hi/lo
    const int g = lane >> 2, tg = lane & 3;
#pragma unroll
    for (int mt = 0; mt < 4; mt++) {
        int r0 = wm + mt * 16 + g;
        int slot0 = bm + r0;
        float gate0 = sgate[r0], gate1 = sgate[r0 + 8];
#pragma unroll
        for (int nt = 0; nt < 4; nt++) {
            int hcol = (bn >> 1) + (wn >> 1) + nt * 4 + tg;
            float gv0 = acc[mt][nt][0], uv0 = acc[mt][nt][1];
            float gv1 = acc[mt][nt][2], uv1 = acc[mt][nt][3];
            float h0 = gate0 * uv0 * (gv0 / (1.f + __expf(-gv0)));
            float h1 = gate1 * uv1 * (gv1 / (1.f + __expf(-gv1)));
            __half hh0 = __float2half(h0);
            __half hh1 = __float2half(h1);
            g_hh[(size_t)slot0 * Idim + hcol]       = hh0;
            g_hl[(size_t)slot0 * Idim + hcol]       = __float2half(h0 - __half2float(hh0));
            g_hh[(size_t)(slot0 + 8) * Idim + hcol] = hh1;
            g_hl[(size_t)(slot0 + 8) * Idim + hcol] = __float2half(h1 - __half2float(hh1));
        }
    }
}

// ================= GEMM2: y = h @ w2^T (2x fp16 mma) -> g_y =================
__global__ void __launch_bounds__(256, 2) gemm2_kernel() {
    extern __shared__ __align__(128) char smem[];
    const uint32_t sb = su32(smem);
    const int tid = threadIdx.x, lane = tid & 31, wid = tid >> 5;
    const int wm = (wid & 1) * 64, wn = (wid >> 1) * 32;
    const int bm = blockIdx.x * 128, bn = blockIdx.y * 128;
    if (bm >= g_off[Edim]) return;
    int e = 0;
#pragma unroll
    for (int i = 1; i < Edim; i++) if (bm >= g_off[i]) e = i;

    const __half* w2_b = g_w2f + ((size_t)(e * Hdim) + bn) * Idim;

    auto load_stage = [&](int kc, int s) {
        const uint32_t base = sb + s * STAGEB;
        const int k0 = kc * 32;
#pragma unroll
        for (int i = 0; i < 2; i++) {
            int idx = tid + i * 256;
            int r = idx >> 2, c = idx & 3;
            uint32_t dof = r * ROWB + c * 16;
            cpa16(base + AH_OF + dof, g_hh + (size_t)(bm + r) * Idim + k0 + c * 8, 16u);
            cpa16(base + AL_OF + dof, g_hl + (size_t)(bm + r) * Idim + k0 + c * 8, 16u);
            cpa16(base + B_OF  + dof, w2_b + (size_t)r * Idim + k0 + c * 8, 16u);
        }
        asm volatile("cp.async.commit_group;" ::: "memory");
    };

    float acc[4][4][4];
#pragma unroll
    for (int a = 0; a < 4; a++)
#pragma unroll
        for (int b = 0; b < 4; b++)
#pragma unroll
            for (int c = 0; c < 4; c++) acc[a][b][c] = 0.f;

    const uint32_t a_off = (lane & 15) * ROWB + (lane >> 4) * 16;
    const uint32_t b_off = (((lane >> 4) << 3) | (lane & 7)) * ROWB + ((lane >> 3) & 1) * 16;

    const int NT = Idim / 32;
    load_stage(0, 0);
    for (int kc = 0; kc < NT; kc++) {
        int s = kc & 1;
        if (kc + 1 < NT) {
            load_stage(kc + 1, s ^ 1);
            asm volatile("cp.async.wait_group 1;" ::: "memory");
        } else {
            asm volatile("cp.async.wait_group 0;" ::: "memory");
        }
        __syncthreads();
        const uint32_t stg = sb + s * STAGEB;
#pragma unroll
        for (int p = 0; p < 2; p++) {
            uint32_t Bv[8];
#pragma unroll
            for (int n2 = 0; n2 < 2; n2++) {
                uint32_t ba = stg + B_OF + (wn + n2 * 16) * ROWB + p * 32 + b_off;
                ldsm4(ba, Bv[n2 * 4 + 0], Bv[n2 * 4 + 1], Bv[n2 * 4 + 2], Bv[n2 * 4 + 3]);
            }
#pragma unroll
            for (int mt = 0; mt < 4; mt++) {
                uint32_t ah[4], al[4];
                uint32_t aa = stg + (wm + mt * 16) * ROWB + p * 32 + a_off;
                ldsm4(aa + AH_OF, ah[0], ah[1], ah[2], ah[3]);
                ldsm4(aa + AL_OF, al[0], al[1], al[2], al[3]);
#pragma unroll
                for (int nt = 0; nt < 4; nt++) {
                    mma16816(acc[mt][nt], ah, &Bv[nt * 2]);
                    mma16816(acc[mt][nt], al, &Bv[nt * 2]);
                }
            }
        }
        __syncthreads();
    }

    // epilogue: write y rows (fp32, float2 per thread)
    const int g = lane >> 2, tg = lane & 3;
#pragma unroll
    for (int mt = 0; mt < 4; mt++) {
        int slot0 = bm + wm + mt * 16 + g;
#pragma unroll
        for (int nt = 0; nt < 4; nt++) {
            int col = bn + wn + nt * 8 + 2 * tg;
            *(float2*)(g_y + (size_t)slot0 * Hdim + col) =
                make_float2(acc[mt][nt][0], acc[mt][nt][1]);
            *(float2*)(g_y + (size_t)(slot0 + 8) * Hdim + col) =
                make_float2(acc[mt][nt][2], acc[mt][nt][3]);
        }
    }
}

// ---------------- combine: out[t] = y[slot0] + y[slot1] ----------------
__global__ void combine_kernel(float* __restrict__ out) {
    int i = blockIdx.x * 256 + threadIdx.x;   // per float4
    int t  = i / (Hdim / 4);
    int c4 = i % (Hdim / 4);
    int s0 = g_slot[t * 2], s1 = g_slot[t * 2 + 1];
    float4 a = *(const float4*)(g_y + (size_t)s0 * Hdim + c4 * 4);
    float4 b = *(const float4*)(g_y + (size_t)s1 * Hdim + c4 * 4);
    *(float4*)(out + (size_t)t * Hdim + c4 * 4) =
        make_float4(a.x + b.x, a.y + b.y, a.z + b.z, a.w + b.w);
}

// ---------------- launch ----------------
extern "C" void kernel_launch(void* const* d_in, const int* in_sizes, int n_in,
                              void* d_out, int out_size) {
    const float* x  = (const float*)d_in[0];
    const float* rw = (const float*)d_in[1];
    const float* w1 = (const float*)d_in[2];
    const float* w2 = (const float*)d_in[3];
    float* out = (float*)d_out;

    cudaFuncSetAttribute(gemm1_kernel, cudaFuncAttributeMaxDynamicSharedMemorySize, SMEM_SZ);
    cudaFuncSetAttribute(gemm2_kernel, cudaFuncAttributeMaxDynamicSharedMemorySize, SMEM_SZ);

    __half *xh, *xl, *w1f, *w2f;
    cudaGetSymbolAddress((void**)&xh,  g_xh);
    cudaGetSymbolAddress((void**)&xl,  g_xl);
    cudaGetSymbolAddress((void**)&w1f, g_w1f);
    cudaGetSymbolAddress((void**)&w2f, g_w2f);

    init_kernel<<<(CAP + 255) / 256, 256>>>();
    {
        size_t n = (size_t)Tdim * Hdim;
        conv_split_kernel<<<(unsigned)((n / 4 + 255) / 256), 256>>>(x, xh, xl, n);
    }
    {
        size_t n = (size_t)Edim * 2 * Idim * Hdim;
        conv_half_kernel<<<(unsigned)((n / 4 + 255) / 256), 256>>>(w1, w1f, n);
    }
    {
        size_t n = (size_t)Edim * Hdim * Idim;
        conv_half_kernel<<<(unsigned)((n / 4 + 255) / 256), 256>>>(w2, w2f, n);
    }
    router_kernel<<<Tdim, 256>>>(x, rw);
    offsets_kernel<<<1, 1>>>();
    scatter_kernel<<<(Tdim + 255) / 256, 256>>>();

    dim3 g1(CAP / 128, (2 * Idim) / 128);
    gemm1_kernel<<<g1, 256, SMEM_SZ>>>();
    dim3 g2(CAP / 128, Hdim / 128);
    gemm2_kernel<<<g2, 256, SMEM_SZ>>>();
    combine_kernel<<<(Tdim * Hdim / 4) / 256, 256>>>(out);
}

// round 12
// speedup vs baseline: 6.5263x; 1.6869x over previous
#include <cuda_runtime.h>
#include <cuda_fp16.h>
#include <math.h>
#include <stdint.h>

#define Tdim 4096
#define Hdim 2048
#define Idim 1024
#define Edim 8
#define CAP  9216   // 8192 assignments + 8*128 padding

// ---------------- device scratch ----------------
__device__ __half g_w1f[(size_t)Edim * 2 * Idim * Hdim];
__device__ __half g_w2f[(size_t)Edim * Hdim * Idim];
__device__ __half g_xf[(size_t)Tdim * Hdim];
__device__ __half g_hf[(size_t)CAP * Idim];
__device__ float g_y[(size_t)CAP * Hdim];
__device__ int   g_tok[CAP];
__device__ float g_gate[CAP];
__device__ int   g_cnt[Edim];
__device__ int   g_off[Edim + 1];
__device__ int   g_fill[Edim];
__device__ int   g_eidx[Tdim * 2];
__device__ float g_gates[Tdim * 2];
__device__ int   g_slot[Tdim * 2];

// ---------------- PTX helpers (plain sm_80-era PTX only) ----------------
__device__ __forceinline__ uint32_t su32(const void* p) {
    uint32_t a;
    asm("{ .reg .u64 t; cvta.to.shared.u64 t, %1; cvt.u32.u64 %0, t; }" : "=r"(a) : "l"(p));
    return a;
}
__device__ __forceinline__ void cpa16(uint32_t dst, const void* src, uint32_t sz) {
    asm volatile("cp.async.cg.shared.global [%0], [%1], 16, %2;\n"
                 :: "r"(dst), "l"(src), "r"(sz) : "memory");
}
__device__ __forceinline__ void ldsm4(uint32_t a, uint32_t& r0, uint32_t& r1,
                                      uint32_t& r2, uint32_t& r3) {
    asm volatile("ldmatrix.sync.aligned.m8n8.x4.shared.b16 {%0,%1,%2,%3}, [%4];"
                 : "=r"(r0), "=r"(r1), "=r"(r2), "=r"(r3) : "r"(a));
}
__device__ __forceinline__ void mma16816(float* d, const uint32_t* a, const uint32_t* b) {
    asm volatile("mma.sync.aligned.m16n8k16.row.col.f32.f16.f16.f32 "
                 "{%0,%1,%2,%3}, {%4,%5,%6,%7}, {%8,%9}, {%0,%1,%2,%3};"
                 : "+f"(d[0]), "+f"(d[1]), "+f"(d[2]), "+f"(d[3])
                 : "r"(a[0]), "r"(a[1]), "r"(a[2]), "r"(a[3]), "r"(b[0]), "r"(b[1]));
}

// SMEM stage layout: 2 matrices (A, B), 128 rows x 64 halfs (128B) + 16B pad = 144B stride
#define ROWB 144
#define MATB (128 * ROWB)        // 18432
#define A_OF 0
#define B_OF MATB
#define STAGEB (2 * MATB)        // 36864
#define SMEM_SZ (2 * STAGEB)     // 73728

// ---------------- init ----------------
__global__ void init_kernel() {
    int i = blockIdx.x * blockDim.x + threadIdx.x;
    if (i < CAP)  { g_tok[i] = -1; g_gate[i] = 0.f; }
    if (i < Edim) g_cnt[i] = 0;
}

// ---------------- fp32 -> fp16 ----------------
__global__ void conv_half_kernel(const float* __restrict__ s,
                                 __half* __restrict__ d, size_t n) {
    size_t i = ((size_t)blockIdx.x * 256 + threadIdx.x) * 4;
    if (i >= n) return;
    float4 v = *(const float4*)(s + i);
    *(__half2*)(d + i)     = __halves2half2(__float2half(v.x), __float2half(v.y));
    *(__half2*)(d + i + 2) = __halves2half2(__float2half(v.z), __float2half(v.w));
}

// ---------------- router ----------------
__global__ void router_kernel(const float* __restrict__ x,
                              const float* __restrict__ rw) {
    const int t   = blockIdx.x;
    const int tid = threadIdx.x;
    float acc[Edim];
#pragma unroll
    for (int e = 0; e < Edim; e++) acc[e] = 0.f;
    const float* xr = x + (size_t)t * Hdim;
    for (int h = tid; h < Hdim; h += 256) {
        float xv = xr[h];
#pragma unroll
        for (int e = 0; e < Edim; e++)
            acc[e] = fmaf(xv, rw[e * Hdim + h], acc[e]);
    }
#pragma unroll
    for (int e = 0; e < Edim; e++)
#pragma unroll
        for (int o = 16; o > 0; o >>= 1)
            acc[e] += __shfl_down_sync(0xffffffffu, acc[e], o);
    __shared__ float s[8][Edim];
    int w = tid >> 5, l = tid & 31;
    if (l == 0)
#pragma unroll
        for (int e = 0; e < Edim; e++) s[w][e] = acc[e];
    __syncthreads();
    if (tid == 0) {
        float logit[Edim];
#pragma unroll
        for (int e = 0; e < Edim; e++) {
            float v = 0.f;
#pragma unroll
            for (int ww = 0; ww < 8; ww++) v += s[ww][e];
            logit[e] = v;
        }
        float m = logit[0];
#pragma unroll
        for (int e = 1; e < Edim; e++) m = fmaxf(m, logit[e]);
        float p[Edim]; float sum = 0.f;
#pragma unroll
        for (int e = 0; e < Edim; e++) { p[e] = expf(logit[e] - m); sum += p[e]; }
        float inv = 1.f / sum;
#pragma unroll
        for (int e = 0; e < Edim; e++) p[e] *= inv;
        int i0 = 0; float p0 = p[0];
#pragma unroll
        for (int e = 1; e < Edim; e++) if (p[e] > p0) { p0 = p[e]; i0 = e; }
        int i1 = -1; float p1 = -1.f;
#pragma unroll
        for (int e = 0; e < Edim; e++)
            if (e != i0 && p[e] > p1) { p1 = p[e]; i1 = e; }
        g_eidx[t * 2 + 0] = i0;  g_gates[t * 2 + 0] = p0;
        g_eidx[t * 2 + 1] = i1;  g_gates[t * 2 + 1] = p1;
        atomicAdd(&g_cnt[i0], 1);
        atomicAdd(&g_cnt[i1], 1);
    }
}

__global__ void offsets_kernel() {
    g_off[0] = 0;
#pragma unroll
    for (int e = 0; e < Edim; e++) {
        g_off[e + 1] = g_off[e] + ((g_cnt[e] + 127) & ~127);
        g_fill[e] = 0;
    }
}

__global__ void scatter_kernel() {
    int t = blockIdx.x * blockDim.x + threadIdx.x;
    if (t >= Tdim) return;
#pragma unroll
    for (int k = 0; k < 2; k++) {
        int e = g_eidx[t * 2 + k];
        int pos = g_off[e] + atomicAdd(&g_fill[e], 1);
        g_tok[pos]  = t;
        g_gate[pos] = g_gates[t * 2 + k];
        g_slot[t * 2 + k] = pos;
    }
}

// ================= GEMM1: up = gather(x) @ w1^T (fp16 mma), SwiGLU*gate -> g_hf =================
__global__ void __launch_bounds__(256, 2) gemm1_kernel() {
    extern __shared__ __align__(128) char smem[];
    __shared__ int   toks[128];
    __shared__ float sgate[128];
    const uint32_t sb = su32(smem);
    const int tid = threadIdx.x, lane = tid & 31, wid = tid >> 5;
    const int wm = (wid & 1) * 64, wn = (wid >> 1) * 32;
    const int bm = blockIdx.x * 128, bn = blockIdx.y * 128;
    if (bm >= g_off[Edim]) return;
    int e = 0;
#pragma unroll
    for (int i = 1; i < Edim; i++) if (bm >= g_off[i]) e = i;
    if (tid < 128) { toks[tid] = g_tok[bm + tid]; sgate[tid] = g_gate[bm + tid]; }
    __syncthreads();

    const __half* w1_b = g_w1f + ((size_t)(e * 2 * Idim) + bn) * Hdim;

    // stage holds K=64: per matrix 128 rows x 128 bytes = 1024 x 16B chunks
    auto load_stage = [&](int kc, int s) {
        const uint32_t base = sb + s * STAGEB;
        const int k0 = kc * 64;
#pragma unroll
        for (int i = 0; i < 4; i++) {
            int idx = tid + i * 256;
            int r = idx >> 3, c = idx & 7;
            int t = toks[r];
            uint32_t sz = (t >= 0) ? 16u : 0u;
            size_t tt = (t >= 0) ? (size_t)t : 0;
            uint32_t dof = r * ROWB + c * 16;
            cpa16(base + A_OF + dof, g_xf + tt * Hdim + k0 + c * 8, sz);
            cpa16(base + B_OF + dof, w1_b + (size_t)r * Hdim + k0 + c * 8, 16u);
        }
        asm volatile("cp.async.commit_group;" ::: "memory");
    };

    float acc[4][4][4];
#pragma unroll
    for (int a = 0; a < 4; a++)
#pragma unroll
        for (int b = 0; b < 4; b++)
#pragma unroll
            for (int c = 0; c < 4; c++) acc[a][b][c] = 0.f;

    const uint32_t a_off = (lane & 15) * ROWB + (lane >> 4) * 16;
    const uint32_t b_off = (((lane >> 4) << 3) | (lane & 7)) * ROWB + ((lane >> 3) & 1) * 16;

    const int NT = Hdim / 64;
    load_stage(0, 0);
    for (int kc = 0; kc < NT; kc++) {
        int s = kc & 1;
        if (kc + 1 < NT) {
            load_stage(kc + 1, s ^ 1);
            asm volatile("cp.async.wait_group 1;" ::: "memory");
        } else {
            asm volatile("cp.async.wait_group 0;" ::: "memory");
        }
        __syncthreads();
        const uint32_t stg = sb + s * STAGEB;
#pragma unroll
        for (int p = 0; p < 4; p++) {
            uint32_t Bv[8];
#pragma unroll
            for (int n2 = 0; n2 < 2; n2++) {
                uint32_t ba = stg + B_OF + (wn + n2 * 16) * ROWB + p * 32 + b_off;
                ldsm4(ba, Bv[n2 * 4 + 0], Bv[n2 * 4 + 1], Bv[n2 * 4 + 2], Bv[n2 * 4 + 3]);
            }
#pragma unroll
            for (int mt = 0; mt < 4; mt++) {
                uint32_t av[4];
                uint32_t aa = stg + A_OF + (wm + mt * 16) * ROWB + p * 32 + a_off;
                ldsm4(aa, av[0], av[1], av[2], av[3]);
#pragma unroll
                for (int nt = 0; nt < 4; nt++)
                    mma16816(acc[mt][nt], av, &Bv[nt * 2]);
            }
        }
        __syncthreads();
    }

    // epilogue: gate * u * silu(g) -> fp16
    const int g = lane >> 2, tg = lane & 3;
#pragma unroll
    for (int mt = 0; mt < 4; mt++) {
        int r0 = wm + mt * 16 + g;
        int slot0 = bm + r0;
        float gate0 = sgate[r0], gate1 = sgate[r0 + 8];
#pragma unroll
        for (int nt = 0; nt < 4; nt++) {
            int hcol = (bn >> 1) + (wn >> 1) + nt * 4 + tg;
            float gv0 = acc[mt][nt][0], uv0 = acc[mt][nt][1];
            float gv1 = acc[mt][nt][2], uv1 = acc[mt][nt][3];
            float h0 = gate0 * uv0 * (gv0 / (1.f + __expf(-gv0)));
            float h1 = gate1 * uv1 * (gv1 / (1.f + __expf(-gv1)));
            g_hf[(size_t)slot0 * Idim + hcol]       = __float2half(h0);
            g_hf[(size_t)(slot0 + 8) * Idim + hcol] = __float2half(h1);
        }
    }
}

// ================= GEMM2: y = h @ w2^T (fp16 mma) -> g_y =================
__global__ void __launch_bounds__(256, 2) gemm2_kernel() {
    extern __shared__ __align__(128) char smem[];
    const uint32_t sb = su32(smem);
    const int tid = threadIdx.x, lane = tid & 31, wid = tid >> 5;
    const int wm = (wid & 1) * 64, wn = (wid >> 1) * 32;
    const int bm = blockIdx.x * 128, bn = blockIdx.y * 128;
    if (bm >= g_off[Edim]) return;
    int e = 0;
#pragma unroll
    for (int i = 1; i < Edim; i++) if (bm >= g_off[i]) e = i;

    const __half* w2_b = g_w2f + ((size_t)(e * Hdim) + bn) * Idim;

    auto load_stage = [&](int kc, int s) {
        const uint32_t base = sb + s * STAGEB;
        const int k0 = kc * 64;
#pragma unroll
        for (int i = 0; i < 4; i++) {
            int idx = tid + i * 256;
            int r = idx >> 3, c = idx & 7;
            uint32_t dof = r * ROWB + c * 16;
            cpa16(base + A_OF + dof, g_hf + (size_t)(bm + r) * Idim + k0 + c * 8, 16u);
            cpa16(base + B_OF + dof, w2_b + (size_t)r * Idim + k0 + c * 8, 16u);
        }
        asm volatile("cp.async.commit_group;" ::: "memory");
    };

    float acc[4][4][4];
#pragma unroll
    for (int a = 0; a < 4; a++)
#pragma unroll
        for (int b = 0; b < 4; b++)
#pragma unroll
            for (int c = 0; c < 4; c++) acc[a][b][c] = 0.f;

    const uint32_t a_off = (lane & 15) * ROWB + (lane >> 4) * 16;
    const uint32_t b_off = (((lane >> 4) << 3) | (lane & 7)) * ROWB + ((lane >> 3) & 1) * 16;

    const int NT = Idim / 64;
    load_stage(0, 0);
    for (int kc = 0; kc < NT; kc++) {
        int s = kc & 1;
        if (kc + 1 < NT) {
            load_stage(kc + 1, s ^ 1);
            asm volatile("cp.async.wait_group 1;" ::: "memory");
        } else {
            asm volatile("cp.async.wait_group 0;" ::: "memory");
        }
        __syncthreads();
        const uint32_t stg = sb + s * STAGEB;
#pragma unroll
        for (int p = 0; p < 4; p++) {
            uint32_t Bv[8];
#pragma unroll
            for (int n2 = 0; n2 < 2; n2++) {
                uint32_t ba = stg + B_OF + (wn + n2 * 16) * ROWB + p * 32 + b_off;
                ldsm4(ba, Bv[n2 * 4 + 0], Bv[n2 * 4 + 1], Bv[n2 * 4 + 2], Bv[n2 * 4 + 3]);
            }
#pragma unroll
            for (int mt = 0; mt < 4; mt++) {
                uint32_t av[4];
                uint32_t aa = stg + A_OF + (wm + mt * 16) * ROWB + p * 32 + a_off;
                ldsm4(aa, av[0], av[1], av[2], av[3]);
#pragma unroll
                for (int nt = 0; nt < 4; nt++)
                    mma16816(acc[mt][nt], av, &Bv[nt * 2]);
            }
        }
        __syncthreads();
    }

    // epilogue: write y rows (fp32, float2 per thread)
    const int g = lane >> 2, tg = lane & 3;
#pragma unroll
    for (int mt = 0; mt < 4; mt++) {
        int slot0 = bm + wm + mt * 16 + g;
#pragma unroll
        for (int nt = 0; nt < 4; nt++) {
            int col = bn + wn + nt * 8 + 2 * tg;
            *(float2*)(g_y + (size_t)slot0 * Hdim + col) =
                make_float2(acc[mt][nt][0], acc[mt][nt][1]);
            *(float2*)(g_y + (size_t)(slot0 + 8) * Hdim + col) =
                make_float2(acc[mt][nt][2], acc[mt][nt][3]);
        }
    }
}

// ---------------- combine: out[t] = y[slot0] + y[slot1] ----------------
__global__ void combine_kernel(float* __restrict__ out) {
    int i = blockIdx.x * 256 + threadIdx.x;   // per float4
    int t  = i / (Hdim / 4);
    int c4 = i % (Hdim / 4);
    int s0 = g_slot[t * 2], s1 = g_slot[t * 2 + 1];
    float4 a = *(const float4*)(g_y + (size_t)s0 * Hdim + c4 * 4);
    float4 b = *(const float4*)(g_y + (size_t)s1 * Hdim + c4 * 4);
    *(float4*)(out + (size_t)t * Hdim + c4 * 4) =
        make_float4(a.x + b.x, a.y + b.y, a.z + b.z, a.w + b.w);
}

// ---------------- launch ----------------
extern "C" void kernel_launch(void* const* d_in, const int* in_sizes, int n_in,
                              void* d_out, int out_size) {
    const float* x  = (const float*)d_in[0];
    const float* rw = (const float*)d_in[1];
    const float* w1 = (const float*)d_in[2];
    const float* w2 = (const float*)d_in[3];
    float* out = (float*)d_out;

    cudaFuncSetAttribute(gemm1_kernel, cudaFuncAttributeMaxDynamicSharedMemorySize, SMEM_SZ);
    cudaFuncSetAttribute(gemm2_kernel, cudaFuncAttributeMaxDynamicSharedMemorySize, SMEM_SZ);

    __half *xf, *w1f, *w2f;
    cudaGetSymbolAddress((void**)&xf,  g_xf);
    cudaGetSymbolAddress((void**)&w1f, g_w1f);
    cudaGetSymbolAddress((void**)&w2f, g_w2f);

    init_kernel<<<(CAP + 255) / 256, 256>>>();
    {
        size_t n = (size_t)Tdim * Hdim;
        conv_half_kernel<<<(unsigned)((n / 4 + 255) / 256), 256>>>(x, xf, n);
    }
    {
        size_t n = (size_t)Edim * 2 * Idim * Hdim;
        conv_half_kernel<<<(unsigned)((n / 4 + 255) / 256), 256>>>(w1, w1f, n);
    }
    {
        size_t n = (size_t)Edim * Hdim * Idim;
        conv_half_kernel<<<(unsigned)((n / 4 + 255) / 256), 256>>>(w2, w2f, n);
    }
    router_kernel<<<Tdim, 256>>>(x, rw);
    offsets_kernel<<<1, 1>>>();
    scatter_kernel<<<(Tdim + 255) / 256, 256>>>();

    dim3 g1(CAP / 128, (2 * Idim) / 128);
    gemm1_kernel<<<g1, 256, SMEM_SZ>>>();
    dim3 g2(CAP / 128, Hdim / 128);
    gemm2_kernel<<<g2, 256, SMEM_SZ>>>();
    combine_kernel<<<(Tdim * Hdim / 4) / 256, 256>>>(out);
}

// round 13
// speedup vs baseline: 6.6501x; 1.0190x over previous
#include <cuda_runtime.h>
#include <cuda_fp16.h>
#include <math.h>
#include <stdint.h>

#define Tdim 4096
#define Hdim 2048
#define Idim 1024
#define Edim 8
#define CAP  9216   // 8192 assignments + 8*128 padding

// ---------------- device scratch ----------------
__device__ __half g_w1f[(size_t)Edim * 2 * Idim * Hdim];
__device__ __half g_w2f[(size_t)Edim * Hdim * Idim];
__device__ __half g_xf[(size_t)Tdim * Hdim];
__device__ __half g_hf[(size_t)CAP * Idim];
__device__ __half g_yh[(size_t)CAP * Hdim];
__device__ int   g_tok[CAP];
__device__ float g_gate[CAP];
__device__ int   g_cnt[Edim];
__device__ int   g_off[Edim + 1];
__device__ int   g_fill[Edim];
__device__ int   g_eidx[Tdim * 2];
__device__ float g_gates[Tdim * 2];
__device__ int   g_slot[Tdim * 2];

// ---------------- PTX helpers (plain sm_80-era PTX only) ----------------
__device__ __forceinline__ uint32_t su32(const void* p) {
    uint32_t a;
    asm("{ .reg .u64 t; cvta.to.shared.u64 t, %1; cvt.u32.u64 %0, t; }" : "=r"(a) : "l"(p));
    return a;
}
__device__ __forceinline__ void cpa16(uint32_t dst, const void* src, uint32_t sz) {
    asm volatile("cp.async.cg.shared.global [%0], [%1], 16, %2;\n"
                 :: "r"(dst), "l"(src), "r"(sz) : "memory");
}
__device__ __forceinline__ void ldsm4(uint32_t a, uint32_t& r0, uint32_t& r1,
                                      uint32_t& r2, uint32_t& r3) {
    asm volatile("ldmatrix.sync.aligned.m8n8.x4.shared.b16 {%0,%1,%2,%3}, [%4];"
                 : "=r"(r0), "=r"(r1), "=r"(r2), "=r"(r3) : "r"(a));
}
__device__ __forceinline__ void mma16816(float* d, const uint32_t* a, const uint32_t* b) {
    asm volatile("mma.sync.aligned.m16n8k16.row.col.f32.f16.f16.f32 "
                 "{%0,%1,%2,%3}, {%4,%5,%6,%7}, {%8,%9}, {%0,%1,%2,%3};"
                 : "+f"(d[0]), "+f"(d[1]), "+f"(d[2]), "+f"(d[3])
                 : "r"(a[0]), "r"(a[1]), "r"(a[2]), "r"(a[3]), "r"(b[0]), "r"(b[1]));
}

// SMEM stage layout: 2 matrices (A, B), 128 rows x 64 halfs (128B) + 16B pad = 144B stride
#define ROWB 144
#define MATB (128 * ROWB)        // 18432
#define A_OF 0
#define B_OF MATB
#define STAGEB (2 * MATB)        // 36864
#define SMEM_SZ (2 * STAGEB)     // 73728

// ---------------- init ----------------
__global__ void init_kernel() {
    int i = blockIdx.x * blockDim.x + threadIdx.x;
    if (i < CAP)  { g_tok[i] = -1; g_gate[i] = 0.f; }
    if (i < Edim) g_cnt[i] = 0;
}

// ---------------- fp32 -> fp16, 8 elems/thread ----------------
__global__ void conv_half_kernel(const float* __restrict__ s,
                                 __half* __restrict__ d, size_t n) {
    size_t i = ((size_t)blockIdx.x * 256 + threadIdx.x) * 8;
    if (i >= n) return;
    float4 v0 = *(const float4*)(s + i);
    float4 v1 = *(const float4*)(s + i + 4);
    __half2 h0 = __floats2half2_rn(v0.x, v0.y);
    __half2 h1 = __floats2half2_rn(v0.z, v0.w);
    __half2 h2 = __floats2half2_rn(v1.x, v1.y);
    __half2 h3 = __floats2half2_rn(v1.z, v1.w);
    uint4 o;
    o.x = *(uint32_t*)&h0; o.y = *(uint32_t*)&h1;
    o.z = *(uint32_t*)&h2; o.w = *(uint32_t*)&h3;
    *(uint4*)(d + i) = o;
}

// ---------------- router ----------------
__global__ void router_kernel(const float* __restrict__ x,
                              const float* __restrict__ rw) {
    const int t   = blockIdx.x;
    const int tid = threadIdx.x;
    float acc[Edim];
#pragma unroll
    for (int e = 0; e < Edim; e++) acc[e] = 0.f;
    const float* xr = x + (size_t)t * Hdim;
    for (int h = tid; h < Hdim; h += 256) {
        float xv = xr[h];
#pragma unroll
        for (int e = 0; e < Edim; e++)
            acc[e] = fmaf(xv, rw[e * Hdim + h], acc[e]);
    }
#pragma unroll
    for (int e = 0; e < Edim; e++)
#pragma unroll
        for (int o = 16; o > 0; o >>= 1)
            acc[e] += __shfl_down_sync(0xffffffffu, acc[e], o);
    __shared__ float s[8][Edim];
    int w = tid >> 5, l = tid & 31;
    if (l == 0)
#pragma unroll
        for (int e = 0; e < Edim; e++) s[w][e] = acc[e];
    __syncthreads();
    if (tid == 0) {
        float logit[Edim];
#pragma unroll
        for (int e = 0; e < Edim; e++) {
            float v = 0.f;
#pragma unroll
            for (int ww = 0; ww < 8; ww++) v += s[ww][e];
            logit[e] = v;
        }
        float m = logit[0];
#pragma unroll
        for (int e = 1; e < Edim; e++) m = fmaxf(m, logit[e]);
        float p[Edim]; float sum = 0.f;
#pragma unroll
        for (int e = 0; e < Edim; e++) { p[e] = expf(logit[e] - m); sum += p[e]; }
        float inv = 1.f / sum;
#pragma unroll
        for (int e = 0; e < Edim; e++) p[e] *= inv;
        int i0 = 0; float p0 = p[0];
#pragma unroll
        for (int e = 1; e < Edim; e++) if (p[e] > p0) { p0 = p[e]; i0 = e; }
        int i1 = -1; float p1 = -1.f;
#pragma unroll
        for (int e = 0; e < Edim; e++)
            if (e != i0 && p[e] > p1) { p1 = p[e]; i1 = e; }
        g_eidx[t * 2 + 0] = i0;  g_gates[t * 2 + 0] = p0;
        g_eidx[t * 2 + 1] = i1;  g_gates[t * 2 + 1] = p1;
        atomicAdd(&g_cnt[i0], 1);
        atomicAdd(&g_cnt[i1], 1);
    }
}

__global__ void offsets_kernel() {
    g_off[0] = 0;
#pragma unroll
    for (int e = 0; e < Edim; e++) {
        g_off[e + 1] = g_off[e] + ((g_cnt[e] + 127) & ~127);
        g_fill[e] = 0;
    }
}

__global__ void scatter_kernel() {
    int t = blockIdx.x * blockDim.x + threadIdx.x;
    if (t >= Tdim) return;
#pragma unroll
    for (int k = 0; k < 2; k++) {
        int e = g_eidx[t * 2 + k];
        int pos = g_off[e] + atomicAdd(&g_fill[e], 1);
        g_tok[pos]  = t;
        g_gate[pos] = g_gates[t * 2 + k];
        g_slot[t * 2 + k] = pos;
    }
}

// ================= GEMM1: up = gather(x) @ w1^T (fp16 mma), SwiGLU*gate -> g_hf =================
__global__ void __launch_bounds__(256, 2) gemm1_kernel() {
    extern __shared__ __align__(128) char smem[];
    __shared__ int   toks[128];
    __shared__ float sgate[128];
    const uint32_t sb = su32(smem);
    const int tid = threadIdx.x, lane = tid & 31, wid = tid >> 5;
    const int wm = (wid & 1) * 64, wn = (wid >> 1) * 32;
    const int bm = blockIdx.x * 128, bn = blockIdx.y * 128;
    if (bm >= g_off[Edim]) return;
    int e = 0;
#pragma unroll
    for (int i = 1; i < Edim; i++) if (bm >= g_off[i]) e = i;
    if (tid < 128) { toks[tid] = g_tok[bm + tid]; sgate[tid] = g_gate[bm + tid]; }
    __syncthreads();

    const __half* w1_b = g_w1f + ((size_t)(e * 2 * Idim) + bn) * Hdim;

    auto load_stage = [&](int kc, int s) {
        const uint32_t base = sb + s * STAGEB;
        const int k0 = kc * 64;
#pragma unroll
        for (int i = 0; i < 4; i++) {
            int idx = tid + i * 256;
            int r = idx >> 3, c = idx & 7;
            int t = toks[r];
            uint32_t sz = (t >= 0) ? 16u : 0u;
            size_t tt = (t >= 0) ? (size_t)t : 0;
            uint32_t dof = r * ROWB + c * 16;
            cpa16(base + A_OF + dof, g_xf + tt * Hdim + k0 + c * 8, sz);
            cpa16(base + B_OF + dof, w1_b + (size_t)r * Hdim + k0 + c * 8, 16u);
        }
        asm volatile("cp.async.commit_group;" ::: "memory");
    };

    float acc[4][4][4];
#pragma unroll
    for (int a = 0; a < 4; a++)
#pragma unroll
        for (int b = 0; b < 4; b++)
#pragma unroll
            for (int c = 0; c < 4; c++) acc[a][b][c] = 0.f;

    const uint32_t a_off = (lane & 15) * ROWB + (lane >> 4) * 16;
    const uint32_t b_off = (((lane >> 4) << 3) | (lane & 7)) * ROWB + ((lane >> 3) & 1) * 16;

    const int NT = Hdim / 64;
    load_stage(0, 0);
    for (int kc = 0; kc < NT; kc++) {
        int s = kc & 1;
        if (kc + 1 < NT) {
            load_stage(kc + 1, s ^ 1);
            asm volatile("cp.async.wait_group 1;" ::: "memory");
        } else {
            asm volatile("cp.async.wait_group 0;" ::: "memory");
        }
        __syncthreads();
        const uint32_t stg = sb + s * STAGEB;
#pragma unroll
        for (int p = 0; p < 4; p++) {
            uint32_t Bv[8];
#pragma unroll
            for (int n2 = 0; n2 < 2; n2++) {
                uint32_t ba = stg + B_OF + (wn + n2 * 16) * ROWB + p * 32 + b_off;
                ldsm4(ba, Bv[n2 * 4 + 0], Bv[n2 * 4 + 1], Bv[n2 * 4 + 2], Bv[n2 * 4 + 3]);
            }
#pragma unroll
            for (int mt = 0; mt < 4; mt++) {
                uint32_t av[4];
                uint32_t aa = stg + A_OF + (wm + mt * 16) * ROWB + p * 32 + a_off;
                ldsm4(aa, av[0], av[1], av[2], av[3]);
#pragma unroll
                for (int nt = 0; nt < 4; nt++)
                    mma16816(acc[mt][nt], av, &Bv[nt * 2]);
            }
        }
        __syncthreads();
    }

    // epilogue: gate * u * silu(g) -> fp16
    const int g = lane >> 2, tg = lane & 3;
#pragma unroll
    for (int mt = 0; mt < 4; mt++) {
        int r0 = wm + mt * 16 + g;
        int slot0 = bm + r0;
        float gate0 = sgate[r0], gate1 = sgate[r0 + 8];
#pragma unroll
        for (int nt = 0; nt < 4; nt++) {
            int hcol = (bn >> 1) + (wn >> 1) + nt * 4 + tg;
            float gv0 = acc[mt][nt][0], uv0 = acc[mt][nt][1];
            float gv1 = acc[mt][nt][2], uv1 = acc[mt][nt][3];
            float h0 = gate0 * uv0 * (gv0 / (1.f + __expf(-gv0)));
            float h1 = gate1 * uv1 * (gv1 / (1.f + __expf(-gv1)));
            g_hf[(size_t)slot0 * Idim + hcol]       = __float2half(h0);
            g_hf[(size_t)(slot0 + 8) * Idim + hcol] = __float2half(h1);
        }
    }
}

// ================= GEMM2: y = h @ w2^T (fp16 mma) -> g_yh (fp16) =================
__global__ void __launch_bounds__(256, 2) gemm2_kernel() {
    extern __shared__ __align__(128) char smem[];
    const uint32_t sb = su32(smem);
    const int tid = threadIdx.x, lane = tid & 31, wid = tid >> 5;
    const int wm = (wid & 1) * 64, wn = (wid >> 1) * 32;
    const int bm = blockIdx.x * 128, bn = blockIdx.y * 128;
    if (bm >= g_off[Edim]) return;
    int e = 0;
#pragma unroll
    for (int i = 1; i < Edim; i++) if (bm >= g_off[i]) e = i;

    const __half* w2_b = g_w2f + ((size_t)(e * Hdim) + bn) * Idim;

    auto load_stage = [&](int kc, int s) {
        const uint32_t base = sb + s * STAGEB;
        const int k0 = kc * 64;
#pragma unroll
        for (int i = 0; i < 4; i++) {
            int idx = tid + i * 256;
            int r = idx >> 3, c = idx & 7;
            uint32_t dof = r * ROWB + c * 16;
            cpa16(base + A_OF + dof, g_hf + (size_t)(bm + r) * Idim + k0 + c * 8, 16u);
            cpa16(base + B_OF + dof, w2_b + (size_t)r * Idim + k0 + c * 8, 16u);
        }
        asm volatile("cp.async.commit_group;" ::: "memory");
    };

    float acc[4][4][4];
#pragma unroll
    for (int a = 0; a < 4; a++)
#pragma unroll
        for (int b = 0; b < 4; b++)
#pragma unroll
            for (int c = 0; c < 4; c++) acc[a][b][c] = 0.f;

    const uint32_t a_off = (lane & 15) * ROWB + (lane >> 4) * 16;
    const uint32_t b_off = (((lane >> 4) << 3) | (lane & 7)) * ROWB + ((lane >> 3) & 1) * 16;

    const int NT = Idim / 64;
    load_stage(0, 0);
    for (int kc = 0; kc < NT; kc++) {
        int s = kc & 1;
        if (kc + 1 < NT) {
            load_stage(kc + 1, s ^ 1);
            asm volatile("cp.async.wait_group 1;" ::: "memory");
        } else {
            asm volatile("cp.async.wait_group 0;" ::: "memory");
        }
        __syncthreads();
        const uint32_t stg = sb + s * STAGEB;
#pragma unroll
        for (int p = 0; p < 4; p++) {
            uint32_t Bv[8];
#pragma unroll
            for (int n2 = 0; n2 < 2; n2++) {
                uint32_t ba = stg + B_OF + (wn + n2 * 16) * ROWB + p * 32 + b_off;
                ldsm4(ba, Bv[n2 * 4 + 0], Bv[n2 * 4 + 1], Bv[n2 * 4 + 2], Bv[n2 * 4 + 3]);
            }
#pragma unroll
            for (int mt = 0; mt < 4; mt++) {
                uint32_t av[4];
                uint32_t aa = stg + A_OF + (wm + mt * 16) * ROWB + p * 32 + a_off;
                ldsm4(aa, av[0], av[1], av[2], av[3]);
#pragma unroll
                for (int nt = 0; nt < 4; nt++)
                    mma16816(acc[mt][nt], av, &Bv[nt * 2]);
            }
        }
        __syncthreads();
    }

    // epilogue: write y rows as fp16 (half2 per thread per row)
    const int g = lane >> 2, tg = lane & 3;
#pragma unroll
    for (int mt = 0; mt < 4; mt++) {
        int slot0 = bm + wm + mt * 16 + g;
#pragma unroll
        for (int nt = 0; nt < 4; nt++) {
            int col = bn + wn + nt * 8 + 2 * tg;
            *(__half2*)(g_yh + (size_t)slot0 * Hdim + col) =
                __floats2half2_rn(acc[mt][nt][0], acc[mt][nt][1]);
            *(__half2*)(g_yh + (size_t)(slot0 + 8) * Hdim + col) =
                __floats2half2_rn(acc[mt][nt][2], acc[mt][nt][3]);
        }
    }
}

// ---------------- combine: out[t] = y[slot0] + y[slot1] (fp16 y, fp32 out) ----------------
__global__ void combine_kernel(float* __restrict__ out) {
    int i = blockIdx.x * 256 + threadIdx.x;   // per 4 outputs
    int t  = i / (Hdim / 4);
    int c4 = i % (Hdim / 4);
    int s0 = g_slot[t * 2], s1 = g_slot[t * 2 + 1];
    uint2 ar = *(const uint2*)(g_yh + (size_t)s0 * Hdim + c4 * 4);
    uint2 br = *(const uint2*)(g_yh + (size_t)s1 * Hdim + c4 * 4);
    float2 a0 = __half22float2(*(__half2*)&ar.x);
    float2 a1 = __half22float2(*(__half2*)&ar.y);
    float2 b0 = __half22float2(*(__half2*)&br.x);
    float2 b1 = __half22float2(*(__half2*)&br.y);
    *(float4*)(out + (size_t)t * Hdim + c4 * 4) =
        make_float4(a0.x + b0.x, a0.y + b0.y, a1.x + b1.x, a1.y + b1.y);
}

// ---------------- launch ----------------
extern "C" void kernel_launch(void* const* d_in, const int* in_sizes, int n_in,
                              void* d_out, int out_size) {
    const float* x  = (const float*)d_in[0];
    const float* rw = (const float*)d_in[1];
    const float* w1 = (const float*)d_in[2];
    const float* w2 = (const float*)d_in[3];
    float* out = (float*)d_out;

    cudaFuncSetAttribute(gemm1_kernel, cudaFuncAttributeMaxDynamicSharedMemorySize, SMEM_SZ);
    cudaFuncSetAttribute(gemm2_kernel, cudaFuncAttributeMaxDynamicSharedMemorySize, SMEM_SZ);

    __half *xf, *w1f, *w2f;
    cudaGetSymbolAddress((void**)&xf,  g_xf);
    cudaGetSymbolAddress((void**)&w1f, g_w1f);
    cudaGetSymbolAddress((void**)&w2f, g_w2f);

    init_kernel<<<(CAP + 255) / 256, 256>>>();
    {
        size_t n = (size_t)Tdim * Hdim;
        conv_half_kernel<<<(unsigned)((n / 8 + 255) / 256), 256>>>(x, xf, n);
    }
    {
        size_t n = (size_t)Edim * 2 * Idim * Hdim;
        conv_half_kernel<<<(unsigned)((n / 8 + 255) / 256), 256>>>(w1, w1f, n);
    }
    {
        size_t n = (size_t)Edim * Hdim * Idim;
        conv_half_kernel<<<(unsigned)((n / 8 + 255) / 256), 256>>>(w2, w2f, n);
    }
    router_kernel<<<Tdim, 256>>>(x, rw);
    offsets_kernel<<<1, 1>>>();
    scatter_kernel<<<(Tdim + 255) / 256, 256>>>();

    dim3 g1(CAP / 128, (2 * Idim) / 128);
    gemm1_kernel<<<g1, 256, SMEM_SZ>>>();
    dim3 g2(CAP / 128, Hdim / 128);
    gemm2_kernel<<<g2, 256, SMEM_SZ>>>();
    combine_kernel<<<(Tdim * Hdim / 4) / 256, 256>>>(out);
}